// round 11
// baseline (speedup 1.0000x reference)
#include <cuda_runtime.h>
#include <math.h>
#include <stdint.h>

#define HID 128
#define STR 132         // padded band row stride (floats) -> conflict-free A frags
#define TPB 128         // 4 warps per block; each warp owns 16 rows independently
#define WB  16          // rows per warp

// scratch: m_i segment sum, per-node A = h@W1a, B = h@W1b
__device__ float g_mi[6500000];
__device__ float g_A[6500000];
__device__ float g_B[6500000];
// fragment-packed tf32 weights: 6 matrices x 4096 uint4
// mats: 0=w_e1a 1=w_e1b 2=w_e2 3=w_h1a 4=w_h1b 5=w_h2
__device__ uint4 g_wpk[24576];

__global__ void zero_mi_kernel(int n4) {
    int i = blockIdx.x * blockDim.x + threadIdx.x;
    if (i < n4) ((float4*)g_mi)[i] = make_float4(0.f, 0.f, 0.f, 0.f);
}

__device__ __forceinline__ uint32_t f2tf(float v) {
    uint32_t t;
    asm("cvt.rna.tf32.f32 %0, %1;" : "=r"(t) : "f"(v));
    return t;
}

// one-shot pack: W[128][128] fp32 -> fragment-ordered tf32 uint4s.
// index i: mat = i>>12; r=i&4095; kkidx=r>>8; jp=(r>>5)&7; lane=r&31; m=lane&3; q=lane>>2
// value lanes need for MMA (kk=8*kkidx, cols 16*jp..+15):
//   {W[kk+m][16jp+q], W[kk+4+m][16jp+q], W[kk+m][16jp+8+q], W[kk+4+m][16jp+8+q]}
__global__ void pack_w_kernel(const float* __restrict__ we1, const float* __restrict__ we2,
                              const float* __restrict__ wh1, const float* __restrict__ wh2) {
    int i = blockIdx.x * blockDim.x + threadIdx.x;
    if (i >= 24576) return;
    int mat = i >> 12;
    int r = i & 4095;
    int kkidx = r >> 8, jp = (r >> 5) & 7, lane = r & 31;
    int m = lane & 3, q = lane >> 2;
    const float* src;
    switch (mat) {
        case 0: src = we1;          break;
        case 1: src = we1 + 16384;  break;
        case 2: src = we2;          break;
        case 3: src = wh1;          break;
        case 4: src = wh1 + 16384;  break;
        default: src = wh2;         break;
    }
    int k0 = kkidx * 8 + m, c0 = jp * 16 + q;
    uint4 v;
    v.x = f2tf(src[k0 * HID + c0]);
    v.y = f2tf(src[(k0 + 4) * HID + c0]);
    v.z = f2tf(src[k0 * HID + c0 + 8]);
    v.w = f2tf(src[(k0 + 4) * HID + c0 + 8]);
    g_wpk[i] = v;
}

__device__ __forceinline__ float silu_f(float v) {
    return v / (1.f + __expf(-v));
}

__device__ __forceinline__ void red_add_v4(float* addr, float a, float b, float c, float d) {
    asm volatile("red.global.add.v4.f32 [%0], {%1, %2, %3, %4};"
                 :: "l"(addr), "f"(a), "f"(b), "f"(c), "f"(d) : "memory");
}

__device__ __forceinline__ void mma_tf32(float* c,
                                         uint32_t a0, uint32_t a1, uint32_t a2, uint32_t a3,
                                         uint32_t b0, uint32_t b1) {
    asm volatile("mma.sync.aligned.m16n8k8.row.col.f32.tf32.tf32.f32 "
                 "{%0,%1,%2,%3}, {%4,%5,%6,%7}, {%8,%9}, {%0,%1,%2,%3};"
                 : "+f"(c[0]), "+f"(c[1]), "+f"(c[2]), "+f"(c[3])
                 : "r"(a0), "r"(a1), "r"(a2), "r"(a3), "r"(b0), "r"(b1));
}

// warp-local: acc[16][4] += band[16 x 128] @ W (fragment-packed).
// A from smem band (fp32 -> tf32 on the fly), B via coalesced LDG.128.
__device__ __forceinline__ void warp_mma_p(const float* __restrict__ band,
                                           const uint4* __restrict__ wp,
                                           float acc[16][4], int lane) {
    const int m = lane & 3, q = lane >> 2;
    #pragma unroll
    for (int kkidx = 0; kkidx < 16; ++kkidx) {
        const float* ar0 = band + q * STR + kkidx * 8 + m;
        uint32_t a0 = f2tf(ar0[0]);
        uint32_t a1 = f2tf(ar0[8 * STR]);
        uint32_t a2 = f2tf(ar0[4]);
        uint32_t a3 = f2tf(ar0[8 * STR + 4]);
        const uint4* w0 = wp + kkidx * 256 + lane;
        #pragma unroll
        for (int jp = 0; jp < 8; ++jp) {
            uint4 b = __ldg(w0 + jp * 32);
            mma_tf32(acc[2 * jp],     a0, a1, a2, a3, b.x, b.y);
            mma_tf32(acc[2 * jp + 1], a0, a1, a2, a3, b.z, b.w);
        }
    }
}

// ---------------------------------------------------------------------------
// Pre kernel: A = h @ W1a, B = h @ W1b. Fully warp-independent.
// ---------------------------------------------------------------------------
__global__ void __launch_bounds__(TPB)
pre_kernel(const float* __restrict__ h, int N) {
    extern __shared__ float sm[];
    const int tid = threadIdx.x;
    const int lane = tid & 31, warp = tid >> 5;
    float* band = sm + warp * WB * STR;
    const int m = lane & 3, q = lane >> 2;
    const long nbase = (long)blockIdx.x * 64 + warp * WB;

    for (int k = 0; k < WB; ++k) {
        long n = nbase + k;
        float4 v = make_float4(0.f, 0.f, 0.f, 0.f);
        if (n < (long)N) v = __ldg((const float4*)(h + n * HID) + lane);
        ((float4*)(band + k * STR))[lane] = v;
    }
    __syncwarp();

    long r0 = nbase + q, r1 = r0 + 8;

    for (int half = 0; half < 2; ++half) {
        float acc[16][4];
        #pragma unroll
        for (int j = 0; j < 16; ++j)
            #pragma unroll
            for (int t = 0; t < 4; ++t) acc[j][t] = 0.f;

        warp_mma_p(band, g_wpk + half * 4096, acc, lane);

        float* dst = half ? g_B : g_A;
        #pragma unroll
        for (int j = 0; j < 16; ++j) {
            int col = j * 8 + 2 * m;
            if (r0 < (long)N) *(float2*)(dst + r0 * HID + col) = make_float2(acc[j][0], acc[j][1]);
            if (r1 < (long)N) *(float2*)(dst + r1 * HID + col) = make_float2(acc[j][2], acc[j][3]);
        }
    }
}

// ---------------------------------------------------------------------------
// Edge kernel: fully warp-independent; 16 edges per warp.
//   m1 = silu(A[s]+B[t]+d*w1d+b1)  fused into gather
//   m2 = silu(m1 @ w2 + b2)        tf32 MMA, B fragment-packed
//   g  = sigmoid(m2 . winf + binf) fragment dot + quad shfl
//   g_mi[s] += g*m2                band round-trip -> red.v4
// ---------------------------------------------------------------------------
__global__ void __launch_bounds__(TPB)
edge_kernel(const float* __restrict__ x, const int* __restrict__ edges,
            const float* __restrict__ w1, const float* __restrict__ b1,
            const float* __restrict__ b2,
            const float* __restrict__ winf, const float* __restrict__ binf,
            int E) {
    extern __shared__ float sm[];
    const int tid = threadIdx.x;
    const int lane = tid & 31, warp = tid >> 5;
    float* band = sm + warp * WB * STR;
    const int m = lane & 3, q = lane >> 2;
    const long ebase = (long)blockIdx.x * 64 + warp * WB;

    int st = -1, en = 0;
    float d = 0.f;
    if (lane < WB) {
        long e = ebase + lane;
        if (e < (long)E) {
            st = edges[2 * e];
            en = edges[2 * e + 1];
            float dx = __ldg(x + 3 * st + 0) - __ldg(x + 3 * en + 0);
            float dy = __ldg(x + 3 * st + 1) - __ldg(x + 3 * en + 1);
            float dz = __ldg(x + 3 * st + 2) - __ldg(x + 3 * en + 2);
            d = sqrtf(dx * dx + dy * dy + dz * dz);
        }
    }

    float4 w1d4 = __ldg((const float4*)(w1 + 256 * HID) + lane);
    float4 b14  = __ldg((const float4*)b1 + lane);
    __syncwarp();

    for (int k = 0; k < WB; ++k) {
        int rs  = __shfl_sync(0xffffffffu, st, k);
        int rt  = __shfl_sync(0xffffffffu, en, k);
        float dd = __shfl_sync(0xffffffffu, d, k);
        float4 v = make_float4(0.f, 0.f, 0.f, 0.f);
        if (rs >= 0) {
            float4 a = __ldg((const float4*)(g_A + (long)rs * HID) + lane);
            float4 b = __ldg((const float4*)(g_B + (long)rt * HID) + lane);
            v.x = silu_f(fmaf(dd, w1d4.x, a.x + b.x) + b14.x);
            v.y = silu_f(fmaf(dd, w1d4.y, a.y + b.y) + b14.y);
            v.z = silu_f(fmaf(dd, w1d4.z, a.z + b.z) + b14.z);
            v.w = silu_f(fmaf(dd, w1d4.w, a.w + b.w) + b14.w);
        }
        ((float4*)(band + k * STR))[lane] = v;
    }
    __syncwarp();

    float acc[16][4];
    #pragma unroll
    for (int j = 0; j < 16; ++j)
        #pragma unroll
        for (int t = 0; t < 4; ++t) acc[j][t] = 0.f;

    warp_mma_p(band, g_wpk + 2 * 4096, acc, lane);

    // bias + silu + gate partial dot (vectorized b2/winf loads)
    float p0 = 0.f, p1 = 0.f;
    #pragma unroll
    for (int j = 0; j < 16; ++j) {
        int col = j * 8 + 2 * m;
        float2 bb = *(const float2*)(b2 + col);
        acc[j][0] = silu_f(acc[j][0] + bb.x);
        acc[j][1] = silu_f(acc[j][1] + bb.y);
        acc[j][2] = silu_f(acc[j][2] + bb.x);
        acc[j][3] = silu_f(acc[j][3] + bb.y);
        float2 wi = *(const float2*)(winf + col);
        p0 = fmaf(acc[j][0], wi.x, fmaf(acc[j][1], wi.y, p0));
        p1 = fmaf(acc[j][2], wi.x, fmaf(acc[j][3], wi.y, p1));
    }
    p0 += __shfl_xor_sync(0xffffffffu, p0, 1);
    p0 += __shfl_xor_sync(0xffffffffu, p0, 2);
    p1 += __shfl_xor_sync(0xffffffffu, p1, 1);
    p1 += __shfl_xor_sync(0xffffffffu, p1, 2);
    float bi = __ldg(binf);
    float g0 = 1.f / (1.f + __expf(-(p0 + bi)));
    float g1 = 1.f / (1.f + __expf(-(p1 + bi)));

    // write g*m2 back to band (own fragment cells), then v4 scatter
    #pragma unroll
    for (int j = 0; j < 16; ++j) {
        int col = j * 8 + 2 * m;
        *(float2*)(band + q * STR + col) =
            make_float2(g0 * acc[j][0], g0 * acc[j][1]);
        *(float2*)(band + (q + 8) * STR + col) =
            make_float2(g1 * acc[j][2], g1 * acc[j][3]);
    }
    __syncwarp();

    {
        int row = lane >> 1, hc = (lane & 1) * 64;
        int str_ = __shfl_sync(0xffffffffu, st, row);
        if (str_ >= 0) {
            const float4* srcr = (const float4*)(band + row * STR + hc);
            float* dst = g_mi + (long)str_ * HID + hc;
            #pragma unroll
            for (int c4 = 0; c4 < 16; ++c4) {
                float4 v = srcr[c4];
                red_add_v4(dst + c4 * 4, v.x, v.y, v.z, v.w);
            }
        }
    }
}

// ---------------------------------------------------------------------------
// Node kernel: h_new = h + (silu([h|m_i] @ wh1 + bh1) @ wh2 + bh2)
// Fully warp-independent; band reused h -> m_i -> u1.
// ---------------------------------------------------------------------------
__global__ void __launch_bounds__(TPB)
node_kernel(const float* __restrict__ h,
            const float* __restrict__ bh1, const float* __restrict__ bh2,
            float* __restrict__ out, int N) {
    extern __shared__ float sm[];
    const int tid = threadIdx.x;
    const int lane = tid & 31, warp = tid >> 5;
    float* band = sm + warp * WB * STR;
    const int m = lane & 3, q = lane >> 2;
    const long nbase = (long)blockIdx.x * 64 + warp * WB;

    for (int k = 0; k < WB; ++k) {
        long n = nbase + k;
        float4 v = make_float4(0.f, 0.f, 0.f, 0.f);
        if (n < (long)N) v = __ldg((const float4*)(h + n * HID) + lane);
        ((float4*)(band + k * STR))[lane] = v;
    }
    __syncwarp();

    float acc[16][4];
    #pragma unroll
    for (int j = 0; j < 16; ++j)
        #pragma unroll
        for (int t = 0; t < 4; ++t) acc[j][t] = 0.f;

    warp_mma_p(band, g_wpk + 3 * 4096, acc, lane);   // K-part from h
    __syncwarp();

    for (int k = 0; k < WB; ++k) {
        long n = nbase + k;
        float4 v = make_float4(0.f, 0.f, 0.f, 0.f);
        if (n < (long)N) v = ((const float4*)(g_mi + n * HID))[lane];
        ((float4*)(band + k * STR))[lane] = v;
    }
    __syncwarp();

    warp_mma_p(band, g_wpk + 4 * 4096, acc, lane);   // K-part from m_i
    __syncwarp();

    #pragma unroll
    for (int j = 0; j < 16; ++j) {
        int col = j * 8 + 2 * m;
        float2 bb = *(const float2*)(bh1 + col);
        *(float2*)(band + q * STR + col) =
            make_float2(silu_f(acc[j][0] + bb.x), silu_f(acc[j][1] + bb.y));
        *(float2*)(band + (q + 8) * STR + col) =
            make_float2(silu_f(acc[j][2] + bb.x), silu_f(acc[j][3] + bb.y));
    }
    __syncwarp();

    float acc2[16][4];
    #pragma unroll
    for (int j = 0; j < 16; ++j)
        #pragma unroll
        for (int t = 0; t < 4; ++t) acc2[j][t] = 0.f;

    warp_mma_p(band, g_wpk + 5 * 4096, acc2, lane);

    long r0 = nbase + q, r1 = r0 + 8;
    #pragma unroll
    for (int j = 0; j < 16; ++j) {
        int col = j * 8 + 2 * m;
        float2 bb = *(const float2*)(bh2 + col);
        if (r0 < (long)N) {
            float2 hv = *(const float2*)(h + r0 * HID + col);
            *(float2*)(out + r0 * HID + col) =
                make_float2(hv.x + acc2[j][0] + bb.x, hv.y + acc2[j][1] + bb.y);
        }
        if (r1 < (long)N) {
            float2 hv = *(const float2*)(h + r1 * HID + col);
            *(float2*)(out + r1 * HID + col) =
                make_float2(hv.x + acc2[j][2] + bb.x, hv.y + acc2[j][3] + bb.y);
        }
    }
}

extern "C" void kernel_launch(void* const* d_in, const int* in_sizes, int n_in,
                              void* d_out, int out_size) {
    const float* h     = (const float*)d_in[0];
    const float* x     = (const float*)d_in[1];
    const int*   edges = (const int*)d_in[2];
    const float* w_e1  = (const float*)d_in[3];
    const float* b_e1  = (const float*)d_in[4];
    const float* w_e2  = (const float*)d_in[5];
    const float* b_e2  = (const float*)d_in[6];
    const float* w_inf = (const float*)d_in[7];
    const float* b_inf = (const float*)d_in[8];
    const float* w_h1  = (const float*)d_in[9];
    const float* b_h1  = (const float*)d_in[10];
    const float* w_h2  = (const float*)d_in[11];
    const float* b_h2  = (const float*)d_in[12];
    float* out = (float*)d_out;

    int N = in_sizes[0] / HID;
    int E = in_sizes[2] / 2;

    const int SMEM = 64 * STR * 4;   // 33792 B: one 16xSTR band per warp

    int n4 = (N * HID) / 4;
    zero_mi_kernel<<<(n4 + 255) / 256, 256>>>(n4);
    pack_w_kernel<<<(24576 + 255) / 256, 256>>>(w_e1, w_e2, w_h1, w_h2);

    pre_kernel<<<(N + 63) / 64, TPB, SMEM>>>(h, N);

    edge_kernel<<<(E + 63) / 64, TPB, SMEM>>>(
        x, edges, w_e1, b_e1, b_e2, w_inf, b_inf, E);

    node_kernel<<<(N + 63) / 64, TPB, SMEM>>>(
        h, b_h1, b_h2, out, N);
}

// round 12
// speedup vs baseline: 1.1414x; 1.1414x over previous
#include <cuda_runtime.h>
#include <math.h>
#include <stdint.h>

#define HID 128
#define STR 132         // padded band row stride (floats) -> conflict-free A frags
#define TPB 128         // 4 warps per block; each warp owns 16 rows independently
#define WB  16          // rows per warp

// scratch: m_i segment sum, per-node A = h@W1a, B = h@W1b
__device__ float g_mi[6500000];
__device__ float g_A[6500000];
__device__ float g_B[6500000];
// fragment-packed tf32 weights: 6 matrices x 4096 uint4
// mats: 0=w_e1a 1=w_e1b 2=w_e2(COLUMN-PERMUTED) 3=w_h1a 4=w_h1b 5=w_h2
__device__ uint4 g_wpk[24576];

__global__ void zero_mi_kernel(int n4) {
    int i = blockIdx.x * blockDim.x + threadIdx.x;
    if (i < n4) ((float4*)g_mi)[i] = make_float4(0.f, 0.f, 0.f, 0.f);
}

__device__ __forceinline__ uint32_t f2tf(float v) {
    uint32_t t;
    asm("cvt.rna.tf32.f32 %0, %1;" : "=r"(t) : "f"(v));
    return t;
}

// one-shot pack: W[128][128] fp32 -> fragment-ordered tf32 uint4s.
// Standard layout (mats 0,1,3,4,5): tile 2jp covers cols 16jp+q (+8 for 2jp+1)
//   -> C-fragment lane (q,m) owns cols {8j+2m, 8j+2m+1}.
// Permuted layout (mat 2, w_e2): tile 2t+p covers cols {16t+2c+p}
//   -> C-fragment lane (q,m) owns 4 CONTIGUOUS cols 16t+4m..+3 across the
//      tile pair, enabling red.v4 scatter straight from fragments.
__global__ void pack_w_kernel(const float* __restrict__ we1, const float* __restrict__ we2,
                              const float* __restrict__ wh1, const float* __restrict__ wh2) {
    int i = blockIdx.x * blockDim.x + threadIdx.x;
    if (i >= 24576) return;
    int mat = i >> 12;
    int r = i & 4095;
    int kkidx = r >> 8, jp = (r >> 5) & 7, lane = r & 31;
    int m = lane & 3, q = lane >> 2;
    const float* src;
    switch (mat) {
        case 0: src = we1;          break;
        case 1: src = we1 + 16384;  break;
        case 2: src = we2;          break;
        case 3: src = wh1;          break;
        case 4: src = wh1 + 16384;  break;
        default: src = wh2;         break;
    }
    int k0 = kkidx * 8 + m;
    int c0, c1;
    if (mat == 2) { c0 = jp * 16 + 2 * q; c1 = c0 + 1; }   // permuted (even/odd split)
    else          { c0 = jp * 16 + q;     c1 = c0 + 8; }   // standard
    uint4 v;
    v.x = f2tf(src[k0 * HID + c0]);
    v.y = f2tf(src[(k0 + 4) * HID + c0]);
    v.z = f2tf(src[k0 * HID + c1]);
    v.w = f2tf(src[(k0 + 4) * HID + c1]);
    g_wpk[i] = v;
}

__device__ __forceinline__ float silu_f(float v) {
    return v / (1.f + __expf(-v));
}

__device__ __forceinline__ void red_add_v4(float* addr, float a, float b, float c, float d) {
    asm volatile("red.global.add.v4.f32 [%0], {%1, %2, %3, %4};"
                 :: "l"(addr), "f"(a), "f"(b), "f"(c), "f"(d) : "memory");
}

__device__ __forceinline__ void mma_tf32(float* c,
                                         uint32_t a0, uint32_t a1, uint32_t a2, uint32_t a3,
                                         uint32_t b0, uint32_t b1) {
    asm volatile("mma.sync.aligned.m16n8k8.row.col.f32.tf32.tf32.f32 "
                 "{%0,%1,%2,%3}, {%4,%5,%6,%7}, {%8,%9}, {%0,%1,%2,%3};"
                 : "+f"(c[0]), "+f"(c[1]), "+f"(c[2]), "+f"(c[3])
                 : "r"(a0), "r"(a1), "r"(a2), "r"(a3), "r"(b0), "r"(b1));
}

// warp-local: acc[16][4] += band[16 x 128] @ W (fragment-packed).
// A from smem band (fp32 -> tf32 on the fly), B via coalesced LDG.128.
__device__ __forceinline__ void warp_mma_p(const float* __restrict__ band,
                                           const uint4* __restrict__ wp,
                                           float acc[16][4], int lane) {
    const int m = lane & 3, q = lane >> 2;
    #pragma unroll
    for (int kkidx = 0; kkidx < 16; ++kkidx) {
        const float* ar0 = band + q * STR + kkidx * 8 + m;
        uint32_t a0 = f2tf(ar0[0]);
        uint32_t a1 = f2tf(ar0[8 * STR]);
        uint32_t a2 = f2tf(ar0[4]);
        uint32_t a3 = f2tf(ar0[8 * STR + 4]);
        const uint4* w0 = wp + kkidx * 256 + lane;
        #pragma unroll
        for (int jp = 0; jp < 8; ++jp) {
            uint4 b = __ldg(w0 + jp * 32);
            mma_tf32(acc[2 * jp],     a0, a1, a2, a3, b.x, b.y);
            mma_tf32(acc[2 * jp + 1], a0, a1, a2, a3, b.z, b.w);
        }
    }
}

// ---------------------------------------------------------------------------
// Pre kernel: A = h @ W1a, B = h @ W1b. Fully warp-independent.
// ---------------------------------------------------------------------------
__global__ void __launch_bounds__(TPB)
pre_kernel(const float* __restrict__ h, int N) {
    extern __shared__ float sm[];
    const int tid = threadIdx.x;
    const int lane = tid & 31, warp = tid >> 5;
    float* band = sm + warp * WB * STR;
    const int m = lane & 3, q = lane >> 2;
    const long nbase = (long)blockIdx.x * 64 + warp * WB;

    for (int k = 0; k < WB; ++k) {
        long n = nbase + k;
        float4 v = make_float4(0.f, 0.f, 0.f, 0.f);
        if (n < (long)N) v = __ldg((const float4*)(h + n * HID) + lane);
        ((float4*)(band + k * STR))[lane] = v;
    }
    __syncwarp();

    long r0 = nbase + q, r1 = r0 + 8;

    for (int half = 0; half < 2; ++half) {
        float acc[16][4];
        #pragma unroll
        for (int j = 0; j < 16; ++j)
            #pragma unroll
            for (int t = 0; t < 4; ++t) acc[j][t] = 0.f;

        warp_mma_p(band, g_wpk + half * 4096, acc, lane);

        float* dst = half ? g_B : g_A;
        #pragma unroll
        for (int j = 0; j < 16; ++j) {
            int col = j * 8 + 2 * m;
            if (r0 < (long)N) *(float2*)(dst + r0 * HID + col) = make_float2(acc[j][0], acc[j][1]);
            if (r1 < (long)N) *(float2*)(dst + r1 * HID + col) = make_float2(acc[j][2], acc[j][3]);
        }
    }
}

// ---------------------------------------------------------------------------
// Edge kernel: fully warp-independent; 16 edges per warp.
//   m1 = silu(A[s]+B[t]+d*w1d+b1)  fused into gather
//   m2 = silu(m1 @ w2 + b2)        tf32 MMA, w2 column-permuted pack
//   g  = sigmoid(m2 . winf + binf) fragment dot + quad shfl
//   g_mi[s] += g*m2                red.v4 straight from fragments
// ---------------------------------------------------------------------------
__global__ void __launch_bounds__(TPB)
edge_kernel(const float* __restrict__ x, const int* __restrict__ edges,
            const float* __restrict__ w1, const float* __restrict__ b1,
            const float* __restrict__ b2,
            const float* __restrict__ winf, const float* __restrict__ binf,
            int E) {
    extern __shared__ float sm[];
    const int tid = threadIdx.x;
    const int lane = tid & 31, warp = tid >> 5;
    float* band = sm + warp * WB * STR;
    const int m = lane & 3, q = lane >> 2;
    const long ebase = (long)blockIdx.x * 64 + warp * WB;

    int st = -1, en = 0;
    float d = 0.f;
    if (lane < WB) {
        long e = ebase + lane;
        if (e < (long)E) {
            st = edges[2 * e];
            en = edges[2 * e + 1];
            float dx = __ldg(x + 3 * st + 0) - __ldg(x + 3 * en + 0);
            float dy = __ldg(x + 3 * st + 1) - __ldg(x + 3 * en + 1);
            float dz = __ldg(x + 3 * st + 2) - __ldg(x + 3 * en + 2);
            d = sqrtf(dx * dx + dy * dy + dz * dz);
        }
    }

    float4 w1d4 = __ldg((const float4*)(w1 + 256 * HID) + lane);
    float4 b14  = __ldg((const float4*)b1 + lane);
    __syncwarp();

    for (int k = 0; k < WB; ++k) {
        int rs  = __shfl_sync(0xffffffffu, st, k);
        int rt  = __shfl_sync(0xffffffffu, en, k);
        float dd = __shfl_sync(0xffffffffu, d, k);
        float4 v = make_float4(0.f, 0.f, 0.f, 0.f);
        if (rs >= 0) {
            float4 a = __ldg((const float4*)(g_A + (long)rs * HID) + lane);
            float4 b = __ldg((const float4*)(g_B + (long)rt * HID) + lane);
            v.x = silu_f(fmaf(dd, w1d4.x, a.x + b.x) + b14.x);
            v.y = silu_f(fmaf(dd, w1d4.y, a.y + b.y) + b14.y);
            v.z = silu_f(fmaf(dd, w1d4.z, a.z + b.z) + b14.z);
            v.w = silu_f(fmaf(dd, w1d4.w, a.w + b.w) + b14.w);
        }
        ((float4*)(band + k * STR))[lane] = v;
    }
    __syncwarp();

    float acc[16][4];
    #pragma unroll
    for (int j = 0; j < 16; ++j)
        #pragma unroll
        for (int t = 0; t < 4; ++t) acc[j][t] = 0.f;

    warp_mma_p(band, g_wpk + 2 * 4096, acc, lane);

    // Permuted mapping: lane (q,m), group t: acc[2t][0],acc[2t+1][0],acc[2t][1],acc[2t+1][1]
    // = real cols 16t+4m .. 16t+4m+3 (row q); elements [2],[3] same cols, row q+8.
    float p0 = 0.f, p1 = 0.f;
    #pragma unroll
    for (int t = 0; t < 8; ++t) {
        float4 bb = __ldg((const float4*)b2 + 4 * t + m);
        float4 wi = __ldg((const float4*)winf + 4 * t + m);
        int ja = 2 * t, jb = 2 * t + 1;
        acc[ja][0] = silu_f(acc[ja][0] + bb.x);
        acc[jb][0] = silu_f(acc[jb][0] + bb.y);
        acc[ja][1] = silu_f(acc[ja][1] + bb.z);
        acc[jb][1] = silu_f(acc[jb][1] + bb.w);
        acc[ja][2] = silu_f(acc[ja][2] + bb.x);
        acc[jb][2] = silu_f(acc[jb][2] + bb.y);
        acc[ja][3] = silu_f(acc[ja][3] + bb.z);
        acc[jb][3] = silu_f(acc[jb][3] + bb.w);
        p0 = fmaf(acc[ja][0], wi.x, fmaf(acc[jb][0], wi.y,
             fmaf(acc[ja][1], wi.z, fmaf(acc[jb][1], wi.w, p0))));
        p1 = fmaf(acc[ja][2], wi.x, fmaf(acc[jb][2], wi.y,
             fmaf(acc[ja][3], wi.z, fmaf(acc[jb][3], wi.w, p1))));
    }
    p0 += __shfl_xor_sync(0xffffffffu, p0, 1);
    p0 += __shfl_xor_sync(0xffffffffu, p0, 2);
    p1 += __shfl_xor_sync(0xffffffffu, p1, 1);
    p1 += __shfl_xor_sync(0xffffffffu, p1, 2);
    float bi = __ldg(binf);
    float g0 = 1.f / (1.f + __expf(-(p0 + bi)));
    float g1 = 1.f / (1.f + __expf(-(p1 + bi)));

    // scatter: 4-contiguous cols per lane per group -> red.v4 from fragments
    int st0 = __shfl_sync(0xffffffffu, st, q);
    int st1 = __shfl_sync(0xffffffffu, st, q + 8);
    if (st0 >= 0) {
        float* dst = g_mi + (long)st0 * HID + 4 * m;
        #pragma unroll
        for (int t = 0; t < 8; ++t)
            red_add_v4(dst + 16 * t,
                       g0 * acc[2 * t][0], g0 * acc[2 * t + 1][0],
                       g0 * acc[2 * t][1], g0 * acc[2 * t + 1][1]);
    }
    if (st1 >= 0) {
        float* dst = g_mi + (long)st1 * HID + 4 * m;
        #pragma unroll
        for (int t = 0; t < 8; ++t)
            red_add_v4(dst + 16 * t,
                       g1 * acc[2 * t][2], g1 * acc[2 * t + 1][2],
                       g1 * acc[2 * t][3], g1 * acc[2 * t + 1][3]);
    }
}

// ---------------------------------------------------------------------------
// Node kernel: h_new = h + (silu([h|m_i] @ wh1 + bh1) @ wh2 + bh2)
// Fully warp-independent; band reused h -> m_i -> u1. (standard pack)
// ---------------------------------------------------------------------------
__global__ void __launch_bounds__(TPB)
node_kernel(const float* __restrict__ h,
            const float* __restrict__ bh1, const float* __restrict__ bh2,
            float* __restrict__ out, int N) {
    extern __shared__ float sm[];
    const int tid = threadIdx.x;
    const int lane = tid & 31, warp = tid >> 5;
    float* band = sm + warp * WB * STR;
    const int m = lane & 3, q = lane >> 2;
    const long nbase = (long)blockIdx.x * 64 + warp * WB;

    for (int k = 0; k < WB; ++k) {
        long n = nbase + k;
        float4 v = make_float4(0.f, 0.f, 0.f, 0.f);
        if (n < (long)N) v = __ldg((const float4*)(h + n * HID) + lane);
        ((float4*)(band + k * STR))[lane] = v;
    }
    __syncwarp();

    float acc[16][4];
    #pragma unroll
    for (int j = 0; j < 16; ++j)
        #pragma unroll
        for (int t = 0; t < 4; ++t) acc[j][t] = 0.f;

    warp_mma_p(band, g_wpk + 3 * 4096, acc, lane);   // K-part from h
    __syncwarp();

    for (int k = 0; k < WB; ++k) {
        long n = nbase + k;
        float4 v = make_float4(0.f, 0.f, 0.f, 0.f);
        if (n < (long)N) v = ((const float4*)(g_mi + n * HID))[lane];
        ((float4*)(band + k * STR))[lane] = v;
    }
    __syncwarp();

    warp_mma_p(band, g_wpk + 4 * 4096, acc, lane);   // K-part from m_i
    __syncwarp();

    #pragma unroll
    for (int j = 0; j < 16; ++j) {
        int col = j * 8 + 2 * m;
        float b0v = __ldg(bh1 + col), b1v = __ldg(bh1 + col + 1);
        *(float2*)(band + q * STR + col) =
            make_float2(silu_f(acc[j][0] + b0v), silu_f(acc[j][1] + b1v));
        *(float2*)(band + (q + 8) * STR + col) =
            make_float2(silu_f(acc[j][2] + b0v), silu_f(acc[j][3] + b1v));
    }
    __syncwarp();

    float acc2[16][4];
    #pragma unroll
    for (int j = 0; j < 16; ++j)
        #pragma unroll
        for (int t = 0; t < 4; ++t) acc2[j][t] = 0.f;

    warp_mma_p(band, g_wpk + 5 * 4096, acc2, lane);

    long r0 = nbase + q, r1 = r0 + 8;
    #pragma unroll
    for (int j = 0; j < 16; ++j) {
        int col = j * 8 + 2 * m;
        float b0v = __ldg(bh2 + col), b1v = __ldg(bh2 + col + 1);
        if (r0 < (long)N) {
            float2 hv = *(const float2*)(h + r0 * HID + col);
            *(float2*)(out + r0 * HID + col) =
                make_float2(hv.x + acc2[j][0] + b0v, hv.y + acc2[j][1] + b1v);
        }
        if (r1 < (long)N) {
            float2 hv = *(const float2*)(h + r1 * HID + col);
            *(float2*)(out + r1 * HID + col) =
                make_float2(hv.x + acc2[j][2] + b0v, hv.y + acc2[j][3] + b1v);
        }
    }
}

extern "C" void kernel_launch(void* const* d_in, const int* in_sizes, int n_in,
                              void* d_out, int out_size) {
    const float* h     = (const float*)d_in[0];
    const float* x     = (const float*)d_in[1];
    const int*   edges = (const int*)d_in[2];
    const float* w_e1  = (const float*)d_in[3];
    const float* b_e1  = (const float*)d_in[4];
    const float* w_e2  = (const float*)d_in[5];
    const float* b_e2  = (const float*)d_in[6];
    const float* w_inf = (const float*)d_in[7];
    const float* b_inf = (const float*)d_in[8];
    const float* w_h1  = (const float*)d_in[9];
    const float* b_h1  = (const float*)d_in[10];
    const float* w_h2  = (const float*)d_in[11];
    const float* b_h2  = (const float*)d_in[12];
    float* out = (float*)d_out;

    int N = in_sizes[0] / HID;
    int E = in_sizes[2] / 2;

    const int SMEM = 64 * STR * 4;   // 33792 B: one 16xSTR band per warp

    int n4 = (N * HID) / 4;
    zero_mi_kernel<<<(n4 + 255) / 256, 256>>>(n4);
    pack_w_kernel<<<(24576 + 255) / 256, 256>>>(w_e1, w_e2, w_h1, w_h2);

    pre_kernel<<<(N + 63) / 64, TPB, SMEM>>>(h, N);

    edge_kernel<<<(E + 63) / 64, TPB, SMEM>>>(
        x, edges, w_e1, b_e1, b_e2, w_inf, b_inf, E);

    node_kernel<<<(N + 63) / 64, TPB, SMEM>>>(
        h, b_h1, b_h2, out, N);
}

// round 15
// speedup vs baseline: 1.2523x; 1.0972x over previous
#include <cuda_runtime.h>
#include <math.h>
#include <stdint.h>

#define HID 128
#define STR 132         // padded band row stride (floats); conflict-free A frags
#define TPB 128         // 4 warps/block; each warp owns 16 rows independently
#define WB  16          // rows per warp

// scratch: m_i segment sum, per-node A = h@W1a, B = h@W1b
__device__ float g_mi[6500000];
__device__ float g_A[6500000];
__device__ float g_B[6500000];
// fragment-packed tf32 weights, 6 matrices x 4096 uint4:
// 0=w_e1a 1=w_e1b 2=w_e2(column-permuted) 3=w_h1a 4=w_h1b 5=w_h2
__device__ uint4 g_wpk[6 * 4096];

__global__ void zero_mi_kernel(int n4) {
    int i = blockIdx.x * blockDim.x + threadIdx.x;
    if (i < n4) ((float4*)g_mi)[i] = make_float4(0.f, 0.f, 0.f, 0.f);
}

__device__ __forceinline__ uint32_t f2tf(float v) {
    uint32_t t;
    asm("cvt.rna.tf32.f32 %0, %1;" : "=r"(t) : "f"(v));
    return t;
}

// One-shot pack of W[128][128] fp32 into fragment-ordered tf32 uint4s.
// Standard (mats 0,1,3,4,5): C-lane (q,m) owns cols {8j+2m, 8j+2m+1}.
// Permuted (mat 2): even/odd column split per 16-col group, so C-lane (q,m)
// owns 4 contiguous cols 16t+4m..+3 -> red.v4 scatter straight from frags.
__global__ void pack_w_kernel(const float* __restrict__ we1, const float* __restrict__ we2,
                              const float* __restrict__ wh1, const float* __restrict__ wh2) {
    int i = blockIdx.x * blockDim.x + threadIdx.x;
    if (i >= 6 * 4096) return;
    int mat = i >> 12;
    int r = i & 4095;
    int kkidx = r >> 8, jp = (r >> 5) & 7, lane = r & 31;
    int m = lane & 3, q = lane >> 2;
    const float* src;
    switch (mat) {
        case 0: src = we1;          break;
        case 1: src = we1 + 16384;  break;
        case 2: src = we2;          break;
        case 3: src = wh1;          break;
        case 4: src = wh1 + 16384;  break;
        default: src = wh2;         break;
    }
    int k0 = kkidx * 8 + m;
    int c0, c1;
    if (mat == 2) { c0 = jp * 16 + 2 * q; c1 = c0 + 1; }
    else          { c0 = jp * 16 + q;     c1 = c0 + 8; }
    uint4 v;
    v.x = f2tf(src[k0 * HID + c0]);
    v.y = f2tf(src[(k0 + 4) * HID + c0]);
    v.z = f2tf(src[k0 * HID + c1]);
    v.w = f2tf(src[(k0 + 4) * HID + c1]);
    g_wpk[i] = v;
}

__device__ __forceinline__ float silu_f(float v) {
    return v / (1.f + __expf(-v));
}

__device__ __forceinline__ void red_add_v4(float* addr, float a, float b, float c, float d) {
    asm volatile("red.global.add.v4.f32 [%0], {%1, %2, %3, %4};"
                 :: "l"(addr), "f"(a), "f"(b), "f"(c), "f"(d) : "memory");
}

__device__ __forceinline__ void mma_tf32(float* c,
                                         uint32_t a0, uint32_t a1, uint32_t a2, uint32_t a3,
                                         uint32_t b0, uint32_t b1) {
    asm volatile("mma.sync.aligned.m16n8k8.row.col.f32.tf32.tf32.f32 "
                 "{%0,%1,%2,%3}, {%4,%5,%6,%7}, {%8,%9}, {%0,%1,%2,%3};"
                 : "+f"(c[0]), "+f"(c[1]), "+f"(c[2]), "+f"(c[3])
                 : "r"(a0), "r"(a1), "r"(a2), "r"(a3), "r"(b0), "r"(b1));
}

// warp-local: acc[16][4] += band[16x128] @ W (fragment-packed, LDG.128 B path)
__device__ __forceinline__ void warp_mma_p(const float* __restrict__ band,
                                           const uint4* __restrict__ wp,
                                           float acc[16][4], int lane) {
    const int m = lane & 3, q = lane >> 2;
    #pragma unroll
    for (int kkidx = 0; kkidx < 16; ++kkidx) {
        const float* ar0 = band + q * STR + kkidx * 8 + m;
        uint32_t a0 = f2tf(ar0[0]);
        uint32_t a1 = f2tf(ar0[8 * STR]);
        uint32_t a2 = f2tf(ar0[4]);
        uint32_t a3 = f2tf(ar0[8 * STR + 4]);
        const uint4* w0 = wp + kkidx * 256 + lane;
        #pragma unroll
        for (int jp = 0; jp < 8; ++jp) {
            uint4 b = __ldg(w0 + jp * 32);
            mma_tf32(acc[2 * jp],     a0, a1, a2, a3, b.x, b.y);
            mma_tf32(acc[2 * jp + 1], a0, a1, a2, a3, b.z, b.w);
        }
    }
}

// ---------------------------------------------------------------------------
// Pre kernel: A = h @ W1a, B = h @ W1b. Warp-independent.
// ---------------------------------------------------------------------------
__global__ void __launch_bounds__(TPB, 5)
pre_kernel(const float* __restrict__ h, int N) {
    extern __shared__ float sm[];
    const int tid = threadIdx.x;
    const int lane = tid & 31, warp = tid >> 5;
    float* band = sm + warp * WB * STR;
    const int m = lane & 3, q = lane >> 2;
    const long nbase = (long)blockIdx.x * 64 + warp * WB;

    for (int k = 0; k < WB; ++k) {
        long n = nbase + k;
        float4 v = make_float4(0.f, 0.f, 0.f, 0.f);
        if (n < (long)N) v = __ldg((const float4*)(h + n * HID) + lane);
        ((float4*)(band + k * STR))[lane] = v;
    }
    __syncwarp();

    long r0 = nbase + q, r1 = r0 + 8;

    for (int half = 0; half < 2; ++half) {
        float acc[16][4];
        #pragma unroll
        for (int j = 0; j < 16; ++j)
            #pragma unroll
            for (int t = 0; t < 4; ++t) acc[j][t] = 0.f;

        warp_mma_p(band, g_wpk + half * 4096, acc, lane);

        float* dst = half ? g_B : g_A;
        #pragma unroll
        for (int j = 0; j < 16; ++j) {
            int col = j * 8 + 2 * m;
            if (r0 < (long)N) *(float2*)(dst + r0 * HID + col) = make_float2(acc[j][0], acc[j][1]);
            if (r1 < (long)N) *(float2*)(dst + r1 * HID + col) = make_float2(acc[j][2], acc[j][3]);
        }
    }
}

// ---------------------------------------------------------------------------
// Edge kernel: warp-independent, 16 edges/warp.
//   m1 = silu(A[s]+B[t]+d*w1d+b1) fused into gather
//   m2 = silu(m1 @ w2 + b2)       tf32 MMA, permuted pack
//   g  = sigmoid(m2 . winf + binf)
//   g_mi[s] += g*m2               red.v4 from fragments
// Launch bounds (TPB,5): cap ~96 regs to keep 5 resident blocks.
// ---------------------------------------------------------------------------
__global__ void __launch_bounds__(TPB, 5)
edge_kernel(const float* __restrict__ x, const int* __restrict__ edges,
            const float* __restrict__ w1, const float* __restrict__ b1,
            const float* __restrict__ b2,
            const float* __restrict__ winf, const float* __restrict__ binf,
            int E) {
    extern __shared__ float sm[];
    const int tid = threadIdx.x;
    const int lane = tid & 31, warp = tid >> 5;
    float* band = sm + warp * WB * STR;
    const int m = lane & 3, q = lane >> 2;
    const long ebase = (long)blockIdx.x * 64 + warp * WB;

    int st = -1, en = 0;
    float d = 0.f;
    if (lane < WB) {
        long e = ebase + lane;
        if (e < (long)E) {
            st = edges[2 * e];
            en = edges[2 * e + 1];
            float dx = __ldg(x + 3 * st + 0) - __ldg(x + 3 * en + 0);
            float dy = __ldg(x + 3 * st + 1) - __ldg(x + 3 * en + 1);
            float dz = __ldg(x + 3 * st + 2) - __ldg(x + 3 * en + 2);
            d = sqrtf(dx * dx + dy * dy + dz * dz);
        }
    }

    float4 w1d4 = __ldg((const float4*)(w1 + 256 * HID) + lane);
    float4 b14  = __ldg((const float4*)b1 + lane);
    __syncwarp();

    for (int k = 0; k < WB; ++k) {
        int rs  = __shfl_sync(0xffffffffu, st, k);
        int rt  = __shfl_sync(0xffffffffu, en, k);
        float dd = __shfl_sync(0xffffffffu, d, k);
        float4 v = make_float4(0.f, 0.f, 0.f, 0.f);
        if (rs >= 0) {
            float4 a = __ldg((const float4*)(g_A + (long)rs * HID) + lane);
            float4 b = __ldg((const float4*)(g_B + (long)rt * HID) + lane);
            v.x = silu_f(fmaf(dd, w1d4.x, a.x + b.x) + b14.x);
            v.y = silu_f(fmaf(dd, w1d4.y, a.y + b.y) + b14.y);
            v.z = silu_f(fmaf(dd, w1d4.z, a.z + b.z) + b14.z);
            v.w = silu_f(fmaf(dd, w1d4.w, a.w + b.w) + b14.w);
        }
        ((float4*)(band + k * STR))[lane] = v;
    }
    __syncwarp();

    float acc[16][4];
    #pragma unroll
    for (int j = 0; j < 16; ++j)
        #pragma unroll
        for (int t = 0; t < 4; ++t) acc[j][t] = 0.f;

    warp_mma_p(band, g_wpk + 2 * 4096, acc, lane);

    // Permuted mapping: group t -> lane (q,m) owns real cols 16t+4m..+3
    // via {acc[2t][0],acc[2t+1][0],acc[2t][1],acc[2t+1][1]} (row q),
    // elements [2],[3] the same cols for row q+8.
    float p0 = 0.f, p1 = 0.f;
    #pragma unroll
    for (int t = 0; t < 8; ++t) {
        float4 bb = __ldg((const float4*)b2 + 4 * t + m);
        float4 wi = __ldg((const float4*)winf + 4 * t + m);
        int ja = 2 * t, jb = 2 * t + 1;
        acc[ja][0] = silu_f(acc[ja][0] + bb.x);
        acc[jb][0] = silu_f(acc[jb][0] + bb.y);
        acc[ja][1] = silu_f(acc[ja][1] + bb.z);
        acc[jb][1] = silu_f(acc[jb][1] + bb.w);
        acc[ja][2] = silu_f(acc[ja][2] + bb.x);
        acc[jb][2] = silu_f(acc[jb][2] + bb.y);
        acc[ja][3] = silu_f(acc[ja][3] + bb.z);
        acc[jb][3] = silu_f(acc[jb][3] + bb.w);
        p0 = fmaf(acc[ja][0], wi.x, fmaf(acc[jb][0], wi.y,
             fmaf(acc[ja][1], wi.z, fmaf(acc[jb][1], wi.w, p0))));
        p1 = fmaf(acc[ja][2], wi.x, fmaf(acc[jb][2], wi.y,
             fmaf(acc[ja][3], wi.z, fmaf(acc[jb][3], wi.w, p1))));
    }
    p0 += __shfl_xor_sync(0xffffffffu, p0, 1);
    p0 += __shfl_xor_sync(0xffffffffu, p0, 2);
    p1 += __shfl_xor_sync(0xffffffffu, p1, 1);
    p1 += __shfl_xor_sync(0xffffffffu, p1, 2);
    float bi = __ldg(binf);
    float g0 = 1.f / (1.f + __expf(-(p0 + bi)));
    float g1 = 1.f / (1.f + __expf(-(p1 + bi)));

    int st0 = __shfl_sync(0xffffffffu, st, q);
    int st1 = __shfl_sync(0xffffffffu, st, q + 8);
    if (st0 >= 0) {
        float* dst = g_mi + (long)st0 * HID + 4 * m;
        #pragma unroll
        for (int t = 0; t < 8; ++t)
            red_add_v4(dst + 16 * t,
                       g0 * acc[2 * t][0], g0 * acc[2 * t + 1][0],
                       g0 * acc[2 * t][1], g0 * acc[2 * t + 1][1]);
    }
    if (st1 >= 0) {
        float* dst = g_mi + (long)st1 * HID + 4 * m;
        #pragma unroll
        for (int t = 0; t < 8; ++t)
            red_add_v4(dst + 16 * t,
                       g1 * acc[2 * t][2], g1 * acc[2 * t + 1][2],
                       g1 * acc[2 * t][3], g1 * acc[2 * t + 1][3]);
    }
}

// ---------------------------------------------------------------------------
// Node kernel: h_new = h + (silu([h|m_i] @ wh1 + bh1) @ wh2 + bh2)
// Warp-independent; band reused h -> m_i -> u1. Standard pack.
// ---------------------------------------------------------------------------
__global__ void __launch_bounds__(TPB)
node_kernel(const float* __restrict__ h,
            const float* __restrict__ bh1, const float* __restrict__ bh2,
            float* __restrict__ out, int N) {
    extern __shared__ float sm[];
    const int tid = threadIdx.x;
    const int lane = tid & 31, warp = tid >> 5;
    float* band = sm + warp * WB * STR;
    const int m = lane & 3, q = lane >> 2;
    const long nbase = (long)blockIdx.x * 64 + warp * WB;

    for (int k = 0; k < WB; ++k) {
        long n = nbase + k;
        float4 v = make_float4(0.f, 0.f, 0.f, 0.f);
        if (n < (long)N) v = __ldg((const float4*)(h + n * HID) + lane);
        ((float4*)(band + k * STR))[lane] = v;
    }
    __syncwarp();

    float acc[16][4];
    #pragma unroll
    for (int j = 0; j < 16; ++j)
        #pragma unroll
        for (int t = 0; t < 4; ++t) acc[j][t] = 0.f;

    warp_mma_p(band, g_wpk + 3 * 4096, acc, lane);
    __syncwarp();

    for (int k = 0; k < WB; ++k) {
        long n = nbase + k;
        float4 v = make_float4(0.f, 0.f, 0.f, 0.f);
        if (n < (long)N) v = ((const float4*)(g_mi + n * HID))[lane];
        ((float4*)(band + k * STR))[lane] = v;
    }
    __syncwarp();

    warp_mma_p(band, g_wpk + 4 * 4096, acc, lane);
    __syncwarp();

    #pragma unroll
    for (int j = 0; j < 16; ++j) {
        int col = j * 8 + 2 * m;
        float b0v = __ldg(bh1 + col), b1v = __ldg(bh1 + col + 1);
        *(float2*)(band + q * STR + col) =
            make_float2(silu_f(acc[j][0] + b0v), silu_f(acc[j][1] + b1v));
        *(float2*)(band + (q + 8) * STR + col) =
            make_float2(silu_f(acc[j][2] + b0v), silu_f(acc[j][3] + b1v));
    }
    __syncwarp();

    float acc2[16][4];
    #pragma unroll
    for (int j = 0; j < 16; ++j)
        #pragma unroll
        for (int t = 0; t < 4; ++t) acc2[j][t] = 0.f;

    warp_mma_p(band, g_wpk + 5 * 4096, acc2, lane);

    long r0 = nbase + q, r1 = r0 + 8;
    #pragma unroll
    for (int j = 0; j < 16; ++j) {
        int col = j * 8 + 2 * m;
        float b0v = __ldg(bh2 + col), b1v = __ldg(bh2 + col + 1);
        if (r0 < (long)N) {
            float2 hv = *(const float2*)(h + r0 * HID + col);
            *(float2*)(out + r0 * HID + col) =
                make_float2(hv.x + acc2[j][0] + b0v, hv.y + acc2[j][1] + b1v);
        }
        if (r1 < (long)N) {
            float2 hv = *(const float2*)(h + r1 * HID + col);
            *(float2*)(out + r1 * HID + col) =
                make_float2(hv.x + acc2[j][2] + b0v, hv.y + acc2[j][3] + b1v);
        }
    }
}

extern "C" void kernel_launch(void* const* d_in, const int* in_sizes, int n_in,
                              void* d_out, int out_size) {
    const float* h     = (const float*)d_in[0];
    const float* x     = (const float*)d_in[1];
    const int*   edges = (const int*)d_in[2];
    const float* w_e1  = (const float*)d_in[3];
    const float* b_e1  = (const float*)d_in[4];
    const float* w_e2  = (const float*)d_in[5];
    const float* b_e2  = (const float*)d_in[6];
    const float* w_inf = (const float*)d_in[7];
    const float* b_inf = (const float*)d_in[8];
    const float* w_h1  = (const float*)d_in[9];
    const float* b_h1  = (const float*)d_in[10];
    const float* w_h2  = (const float*)d_in[11];
    const float* b_h2  = (const float*)d_in[12];
    float* out = (float*)d_out;

    int N = in_sizes[0] / HID;
    int E = in_sizes[2] / 2;

    const int SMEM = 64 * STR * 4;   // one 16xSTR fp32 band per warp

    int n4 = (N * HID) / 4;
    zero_mi_kernel<<<(n4 + 255) / 256, 256>>>(n4);
    pack_w_kernel<<<(6 * 4096 + 255) / 256, 256>>>(w_e1, w_e2, w_h1, w_h2);

    pre_kernel<<<(N + 63) / 64, TPB, SMEM>>>(h, N);

    edge_kernel<<<(E + 63) / 64, TPB, SMEM>>>(
        x, edges, w_e1, b_e1, b_e2, w_inf, b_inf, E);

    node_kernel<<<(N + 63) / 64, TPB, SMEM>>>(
        h, b_h1, b_h2, out, N);
}

// round 16
// speedup vs baseline: 1.5702x; 1.2538x over previous
#include <cuda_runtime.h>
#include <math.h>
#include <stdint.h>

#define HID 128
#define STR 132         // padded band row stride (floats); conflict-free A frags
#define TPB 128         // 4 warps/block; each warp owns 16 rows independently
#define WB  16          // rows per warp

// scratch: m_i segment sum, per-node A = h@W1a, B = h@W1b
__device__ float g_mi[6500000];
__device__ float g_A[6500000];
__device__ float g_B[6500000];
// fragment-packed tf32 weights, 6 matrices x 4096 uint4:
// 0=w_e1a 1=w_e1b 2=w_e2(column-permuted) 3=w_h1a 4=w_h1b 5=w_h2
__device__ uint4 g_wpk[6 * 4096];

__global__ void zero_mi_kernel(int n4) {
    int i = blockIdx.x * blockDim.x + threadIdx.x;
    if (i < n4) ((float4*)g_mi)[i] = make_float4(0.f, 0.f, 0.f, 0.f);
}

__device__ __forceinline__ uint32_t f2tf(float v) {
    uint32_t t;
    asm("cvt.rna.tf32.f32 %0, %1;" : "=r"(t) : "f"(v));
    return t;
}

// One-shot pack of W[128][128] fp32 into fragment-ordered tf32 uint4s.
// Standard (mats 0,1,3,4,5): C-lane (q,m) owns cols {8j+2m, 8j+2m+1}.
// Permuted (mat 2): even/odd column split per 16-col group, so C-lane (q,m)
// owns 4 contiguous cols 16t+4m..+3 -> red.v4 scatter straight from frags.
__global__ void pack_w_kernel(const float* __restrict__ we1, const float* __restrict__ we2,
                              const float* __restrict__ wh1, const float* __restrict__ wh2) {
    int i = blockIdx.x * blockDim.x + threadIdx.x;
    if (i >= 6 * 4096) return;
    int mat = i >> 12;
    int r = i & 4095;
    int kkidx = r >> 8, jp = (r >> 5) & 7, lane = r & 31;
    int m = lane & 3, q = lane >> 2;
    const float* src;
    switch (mat) {
        case 0: src = we1;          break;
        case 1: src = we1 + 16384;  break;
        case 2: src = we2;          break;
        case 3: src = wh1;          break;
        case 4: src = wh1 + 16384;  break;
        default: src = wh2;         break;
    }
    int k0 = kkidx * 8 + m;
    int c0, c1;
    if (mat == 2) { c0 = jp * 16 + 2 * q; c1 = c0 + 1; }
    else          { c0 = jp * 16 + q;     c1 = c0 + 8; }
    uint4 v;
    v.x = f2tf(src[k0 * HID + c0]);
    v.y = f2tf(src[(k0 + 4) * HID + c0]);
    v.z = f2tf(src[k0 * HID + c1]);
    v.w = f2tf(src[(k0 + 4) * HID + c1]);
    g_wpk[i] = v;
}

// fast silu: MUFU.EX2-based exp + MUFU.RCP-based divide (2 instr, ~2ulp)
__device__ __forceinline__ float silu_f(float v) {
    return __fdividef(v, 1.f + __expf(-v));
}

__device__ __forceinline__ float sigmoid_f(float v) {
    return __fdividef(1.f, 1.f + __expf(-v));
}

__device__ __forceinline__ void red_add_v4(float* addr, float a, float b, float c, float d) {
    asm volatile("red.global.add.v4.f32 [%0], {%1, %2, %3, %4};"
                 :: "l"(addr), "f"(a), "f"(b), "f"(c), "f"(d) : "memory");
}

__device__ __forceinline__ void mma_tf32(float* c,
                                         uint32_t a0, uint32_t a1, uint32_t a2, uint32_t a3,
                                         uint32_t b0, uint32_t b1) {
    asm volatile("mma.sync.aligned.m16n8k8.row.col.f32.tf32.tf32.f32 "
                 "{%0,%1,%2,%3}, {%4,%5,%6,%7}, {%8,%9}, {%0,%1,%2,%3};"
                 : "+f"(c[0]), "+f"(c[1]), "+f"(c[2]), "+f"(c[3])
                 : "r"(a0), "r"(a1), "r"(a2), "r"(a3), "r"(b0), "r"(b1));
}

// warp-local: acc[16][4] += band[16x128] @ W (fragment-packed, LDG.128 B path)
__device__ __forceinline__ void warp_mma_p(const float* __restrict__ band,
                                           const uint4* __restrict__ wp,
                                           float acc[16][4], int lane) {
    const int m = lane & 3, q = lane >> 2;
    #pragma unroll
    for (int kkidx = 0; kkidx < 16; ++kkidx) {
        const float* ar0 = band + q * STR + kkidx * 8 + m;
        uint32_t a0 = f2tf(ar0[0]);
        uint32_t a1 = f2tf(ar0[8 * STR]);
        uint32_t a2 = f2tf(ar0[4]);
        uint32_t a3 = f2tf(ar0[8 * STR + 4]);
        const uint4* w0 = wp + kkidx * 256 + lane;
        #pragma unroll
        for (int jp = 0; jp < 8; ++jp) {
            uint4 b = __ldg(w0 + jp * 32);
            mma_tf32(acc[2 * jp],     a0, a1, a2, a3, b.x, b.y);
            mma_tf32(acc[2 * jp + 1], a0, a1, a2, a3, b.z, b.w);
        }
    }
}

// ---------------------------------------------------------------------------
// Pre kernel: A = h @ W1a, B = h @ W1b. Warp-independent.
// ---------------------------------------------------------------------------
__global__ void __launch_bounds__(TPB, 5)
pre_kernel(const float* __restrict__ h, int N) {
    extern __shared__ float sm[];
    const int tid = threadIdx.x;
    const int lane = tid & 31, warp = tid >> 5;
    float* band = sm + warp * WB * STR;
    const int m = lane & 3, q = lane >> 2;
    const long nbase = (long)blockIdx.x * 64 + warp * WB;

    for (int k = 0; k < WB; ++k) {
        long n = nbase + k;
        float4 v = make_float4(0.f, 0.f, 0.f, 0.f);
        if (n < (long)N) v = __ldg((const float4*)(h + n * HID) + lane);
        ((float4*)(band + k * STR))[lane] = v;
    }
    __syncwarp();

    long r0 = nbase + q, r1 = r0 + 8;

    for (int half = 0; half < 2; ++half) {
        float acc[16][4];
        #pragma unroll
        for (int j = 0; j < 16; ++j)
            #pragma unroll
            for (int t = 0; t < 4; ++t) acc[j][t] = 0.f;

        warp_mma_p(band, g_wpk + half * 4096, acc, lane);

        float* dst = half ? g_B : g_A;
        #pragma unroll
        for (int j = 0; j < 16; ++j) {
            int col = j * 8 + 2 * m;
            if (r0 < (long)N) *(float2*)(dst + r0 * HID + col) = make_float2(acc[j][0], acc[j][1]);
            if (r1 < (long)N) *(float2*)(dst + r1 * HID + col) = make_float2(acc[j][2], acc[j][3]);
        }
    }
}

// ---------------------------------------------------------------------------
// Edge kernel: warp-independent, 16 edges/warp.
//   m1 = silu(A[s]+B[t]+d*w1d+b1) fused into gather
//   m2 = silu(m1 @ w2 + b2)       tf32 MMA, permuted pack
//   g  = sigmoid(m2 . winf + binf)
//   g_mi[s] += g*m2               red.v4 from fragments
// Launch bounds (TPB,5): cap ~96 regs to keep 5 resident blocks.
// ---------------------------------------------------------------------------
__global__ void __launch_bounds__(TPB, 5)
edge_kernel(const float* __restrict__ x, const int* __restrict__ edges,
            const float* __restrict__ w1, const float* __restrict__ b1,
            const float* __restrict__ b2,
            const float* __restrict__ winf, const float* __restrict__ binf,
            int E) {
    extern __shared__ float sm[];
    const int tid = threadIdx.x;
    const int lane = tid & 31, warp = tid >> 5;
    float* band = sm + warp * WB * STR;
    const int m = lane & 3, q = lane >> 2;
    const long ebase = (long)blockIdx.x * 64 + warp * WB;

    int st = -1, en = 0;
    float d = 0.f;
    if (lane < WB) {
        long e = ebase + lane;
        if (e < (long)E) {
            st = edges[2 * e];
            en = edges[2 * e + 1];
            float dx = __ldg(x + 3 * st + 0) - __ldg(x + 3 * en + 0);
            float dy = __ldg(x + 3 * st + 1) - __ldg(x + 3 * en + 1);
            float dz = __ldg(x + 3 * st + 2) - __ldg(x + 3 * en + 2);
            d = sqrtf(dx * dx + dy * dy + dz * dz);
        }
    }

    float4 w1d4 = __ldg((const float4*)(w1 + 256 * HID) + lane);
    float4 b14  = __ldg((const float4*)b1 + lane);
    __syncwarp();

    for (int k = 0; k < WB; ++k) {
        int rs  = __shfl_sync(0xffffffffu, st, k);
        int rt  = __shfl_sync(0xffffffffu, en, k);
        float dd = __shfl_sync(0xffffffffu, d, k);
        float4 v = make_float4(0.f, 0.f, 0.f, 0.f);
        if (rs >= 0) {
            float4 a = __ldg((const float4*)(g_A + (long)rs * HID) + lane);
            float4 b = __ldg((const float4*)(g_B + (long)rt * HID) + lane);
            v.x = silu_f(fmaf(dd, w1d4.x, a.x + b.x) + b14.x);
            v.y = silu_f(fmaf(dd, w1d4.y, a.y + b.y) + b14.y);
            v.z = silu_f(fmaf(dd, w1d4.z, a.z + b.z) + b14.z);
            v.w = silu_f(fmaf(dd, w1d4.w, a.w + b.w) + b14.w);
        }
        ((float4*)(band + k * STR))[lane] = v;
    }
    __syncwarp();

    float acc[16][4];
    #pragma unroll
    for (int j = 0; j < 16; ++j)
        #pragma unroll
        for (int t = 0; t < 4; ++t) acc[j][t] = 0.f;

    warp_mma_p(band, g_wpk + 2 * 4096, acc, lane);

    // Permuted mapping: group t -> lane (q,m) owns real cols 16t+4m..+3
    // via {acc[2t][0],acc[2t+1][0],acc[2t][1],acc[2t+1][1]} (row q),
    // elements [2],[3] the same cols for row q+8.
    float p0 = 0.f, p1 = 0.f;
    #pragma unroll
    for (int t = 0; t < 8; ++t) {
        float4 bb = __ldg((const float4*)b2 + 4 * t + m);
        float4 wi = __ldg((const float4*)winf + 4 * t + m);
        int ja = 2 * t, jb = 2 * t + 1;
        acc[ja][0] = silu_f(acc[ja][0] + bb.x);
        acc[jb][0] = silu_f(acc[jb][0] + bb.y);
        acc[ja][1] = silu_f(acc[ja][1] + bb.z);
        acc[jb][1] = silu_f(acc[jb][1] + bb.w);
        acc[ja][2] = silu_f(acc[ja][2] + bb.x);
        acc[jb][2] = silu_f(acc[jb][2] + bb.y);
        acc[ja][3] = silu_f(acc[ja][3] + bb.z);
        acc[jb][3] = silu_f(acc[jb][3] + bb.w);
        p0 = fmaf(acc[ja][0], wi.x, fmaf(acc[jb][0], wi.y,
             fmaf(acc[ja][1], wi.z, fmaf(acc[jb][1], wi.w, p0))));
        p1 = fmaf(acc[ja][2], wi.x, fmaf(acc[jb][2], wi.y,
             fmaf(acc[ja][3], wi.z, fmaf(acc[jb][3], wi.w, p1))));
    }
    p0 += __shfl_xor_sync(0xffffffffu, p0, 1);
    p0 += __shfl_xor_sync(0xffffffffu, p0, 2);
    p1 += __shfl_xor_sync(0xffffffffu, p1, 1);
    p1 += __shfl_xor_sync(0xffffffffu, p1, 2);
    float bi = __ldg(binf);
    float g0 = sigmoid_f(p0 + bi);
    float g1 = sigmoid_f(p1 + bi);

    int st0 = __shfl_sync(0xffffffffu, st, q);
    int st1 = __shfl_sync(0xffffffffu, st, q + 8);
    if (st0 >= 0) {
        float* dst = g_mi + (long)st0 * HID + 4 * m;
        #pragma unroll
        for (int t = 0; t < 8; ++t)
            red_add_v4(dst + 16 * t,
                       g0 * acc[2 * t][0], g0 * acc[2 * t + 1][0],
                       g0 * acc[2 * t][1], g0 * acc[2 * t + 1][1]);
    }
    if (st1 >= 0) {
        float* dst = g_mi + (long)st1 * HID + 4 * m;
        #pragma unroll
        for (int t = 0; t < 8; ++t)
            red_add_v4(dst + 16 * t,
                       g1 * acc[2 * t][2], g1 * acc[2 * t + 1][2],
                       g1 * acc[2 * t][3], g1 * acc[2 * t + 1][3]);
    }
}

// ---------------------------------------------------------------------------
// Node kernel: h_new = h + (silu([h|m_i] @ wh1 + bh1) @ wh2 + bh2)
// Warp-independent; band reused h -> m_i -> u1. Standard pack.
// ---------------------------------------------------------------------------
__global__ void __launch_bounds__(TPB)
node_kernel(const float* __restrict__ h,
            const float* __restrict__ bh1, const float* __restrict__ bh2,
            float* __restrict__ out, int N) {
    extern __shared__ float sm[];
    const int tid = threadIdx.x;
    const int lane = tid & 31, warp = tid >> 5;
    float* band = sm + warp * WB * STR;
    const int m = lane & 3, q = lane >> 2;
    const long nbase = (long)blockIdx.x * 64 + warp * WB;

    for (int k = 0; k < WB; ++k) {
        long n = nbase + k;
        float4 v = make_float4(0.f, 0.f, 0.f, 0.f);
        if (n < (long)N) v = __ldg((const float4*)(h + n * HID) + lane);
        ((float4*)(band + k * STR))[lane] = v;
    }
    __syncwarp();

    float acc[16][4];
    #pragma unroll
    for (int j = 0; j < 16; ++j)
        #pragma unroll
        for (int t = 0; t < 4; ++t) acc[j][t] = 0.f;

    warp_mma_p(band, g_wpk + 3 * 4096, acc, lane);
    __syncwarp();

    for (int k = 0; k < WB; ++k) {
        long n = nbase + k;
        float4 v = make_float4(0.f, 0.f, 0.f, 0.f);
        if (n < (long)N) v = ((const float4*)(g_mi + n * HID))[lane];
        ((float4*)(band + k * STR))[lane] = v;
    }
    __syncwarp();

    warp_mma_p(band, g_wpk + 4 * 4096, acc, lane);
    __syncwarp();

    #pragma unroll
    for (int j = 0; j < 16; ++j) {
        int col = j * 8 + 2 * m;
        float b0v = __ldg(bh1 + col), b1v = __ldg(bh1 + col + 1);
        *(float2*)(band + q * STR + col) =
            make_float2(silu_f(acc[j][0] + b0v), silu_f(acc[j][1] + b1v));
        *(float2*)(band + (q + 8) * STR + col) =
            make_float2(silu_f(acc[j][2] + b0v), silu_f(acc[j][3] + b1v));
    }
    __syncwarp();

    float acc2[16][4];
    #pragma unroll
    for (int j = 0; j < 16; ++j)
        #pragma unroll
        for (int t = 0; t < 4; ++t) acc2[j][t] = 0.f;

    warp_mma_p(band, g_wpk + 5 * 4096, acc2, lane);

    long r0 = nbase + q, r1 = r0 + 8;
    #pragma unroll
    for (int j = 0; j < 16; ++j) {
        int col = j * 8 + 2 * m;
        float b0v = __ldg(bh2 + col), b1v = __ldg(bh2 + col + 1);
        if (r0 < (long)N) {
            float2 hv = *(const float2*)(h + r0 * HID + col);
            *(float2*)(out + r0 * HID + col) =
                make_float2(hv.x + acc2[j][0] + b0v, hv.y + acc2[j][1] + b1v);
        }
        if (r1 < (long)N) {
            float2 hv = *(const float2*)(h + r1 * HID + col);
            *(float2*)(out + r1 * HID + col) =
                make_float2(hv.x + acc2[j][2] + b0v, hv.y + acc2[j][3] + b1v);
        }
    }
}

extern "C" void kernel_launch(void* const* d_in, const int* in_sizes, int n_in,
                              void* d_out, int out_size) {
    const float* h     = (const float*)d_in[0];
    const float* x     = (const float*)d_in[1];
    const int*   edges = (const int*)d_in[2];
    const float* w_e1  = (const float*)d_in[3];
    const float* b_e1  = (const float*)d_in[4];
    const float* w_e2  = (const float*)d_in[5];
    const float* b_e2  = (const float*)d_in[6];
    const float* w_inf = (const float*)d_in[7];
    const float* b_inf = (const float*)d_in[8];
    const float* w_h1  = (const float*)d_in[9];
    const float* b_h1  = (const float*)d_in[10];
    const float* w_h2  = (const float*)d_in[11];
    const float* b_h2  = (const float*)d_in[12];
    float* out = (float*)d_out;

    int N = in_sizes[0] / HID;
    int E = in_sizes[2] / 2;

    const int SMEM = 64 * STR * 4;   // one 16xSTR fp32 band per warp

    int n4 = (N * HID) / 4;
    zero_mi_kernel<<<(n4 + 255) / 256, 256>>>(n4);
    pack_w_kernel<<<(6 * 4096 + 255) / 256, 256>>>(w_e1, w_e2, w_h1, w_h2);

    pre_kernel<<<(N + 63) / 64, TPB, SMEM>>>(h, N);

    edge_kernel<<<(E + 63) / 64, TPB, SMEM>>>(
        x, edges, w_e1, b_e1, b_e2, w_inf, b_inf, E);

    node_kernel<<<(N + 63) / 64, TPB, SMEM>>>(
        h, b_h1, b_h2, out, N);
}